// round 9
// baseline (speedup 1.0000x reference)
#include <cuda_runtime.h>
#include <cuda_fp16.h>

#define BB 2
#define CC 8
#define HH 512
#define WW 1024
#define OC 8
#define KY 3
#define KX 3
#define KK (KY*KX)
#define HW (HH*WW)

// fp16 transposed input: [b][pix] -> 8 channels packed in 16 bytes.
__device__ __align__(16) uint4 g_h[(size_t)BB * HW];

__global__ __launch_bounds__(256) void transpose_h(const float* __restrict__ x) {
    int idx = blockIdx.x * 256 + threadIdx.x;
    if (idx >= BB * HW) return;
    int b = idx >> 19;
    int hw = idx & (HW - 1);
    const float* xp = x + (size_t)b * CC * HW + hw;
    __half2 p0 = __floats2half2_rn(xp[0 * HW], xp[1 * HW]);
    __half2 p1 = __floats2half2_rn(xp[2 * HW], xp[3 * HW]);
    __half2 p2 = __floats2half2_rn(xp[4 * HW], xp[5 * HW]);
    __half2 p3 = __floats2half2_rn(xp[6 * HW], xp[7 * HW]);
    uint4 q;
    q.x = *reinterpret_cast<unsigned*>(&p0);
    q.y = *reinterpret_cast<unsigned*>(&p1);
    q.z = *reinterpret_cast<unsigned*>(&p2);
    q.w = *reinterpret_cast<unsigned*>(&p3);
    g_h[idx] = q;
}

// atan2 with single fast division + Cephes poly. ~1e-7 rad error.
// Returns exactly +/-0 when y == 0 and x > 0 (relied on for the fx==0 path).
__device__ __forceinline__ float fast_atan2f(float y, float x) {
    float ay = fabsf(y), ax = fabsf(x);
    float n = fminf(ay, ax), d = fmaxf(ay, ax);
    bool big = n > 0.4142135624f * d;
    float num = big ? (n - d) : n;
    float den = big ? (n + d) : d;
    float t = __fdividef(num, den);
    float z = t * t;
    float p = fmaf(fmaf(fmaf(8.05374449538e-2f, z, -1.38776856032e-1f), z,
                        1.99777106478e-1f), z, -3.33329491539e-1f);
    float r = fmaf(p * z, t, t);
    if (big) r += 0.78539816339744831f;
    if (ay > ax) r = 1.57079632679489662f - r;
    if (x < 0.0f) r = 3.14159265358979323f - r;
    return copysignf(r, y);
}

__device__ __forceinline__ unsigned long long dup_f32x2(float f) {
    unsigned long long r;
    asm("mov.b64 %0, {%1, %1};" : "=l"(r) : "f"(f));
    return r;
}

__device__ __forceinline__ void ffma2(unsigned long long& acc,
                                      unsigned long long a, unsigned long long b) {
    asm("fma.rn.f32x2 %0, %1, %2, %0;" : "+l"(acc) : "l"(a), "l"(b));
}

__device__ __forceinline__ __half2 u2h2(unsigned u) { return *reinterpret_cast<__half2*>(&u); }

// 4-tap bilinear over 8 fp16 channels -> 4 half2 (kept in fp16)
__device__ __forceinline__ void blend4h(uint4 A, uint4 B, uint4 C, uint4 D,
                                        __half2 w00, __half2 w01, __half2 w10, __half2 w11,
                                        __half2* o) {
    const __half2* a = reinterpret_cast<const __half2*>(&A);
    const __half2* b = reinterpret_cast<const __half2*>(&B);
    const __half2* c = reinterpret_cast<const __half2*>(&C);
    const __half2* d = reinterpret_cast<const __half2*>(&D);
#pragma unroll
    for (int j = 0; j < 4; j++) {
        __half2 t = __hmul2(a[j], w00);
        t = __hfma2(b[j], w01, t);
        t = __hfma2(c[j], w10, t);
        o[j] = __hfma2(d[j], w11, t);
    }
}

// 2-tap (y only): fx == 0 exact path
__device__ __forceinline__ void blend2h(uint4 A, uint4 B,
                                        __half2 wy0, __half2 wy1, __half2* o) {
    const __half2* a = reinterpret_cast<const __half2*>(&A);
    const __half2* b = reinterpret_cast<const __half2*>(&B);
#pragma unroll
    for (int j = 0; j < 4; j++)
        o[j] = __hfma2(b[j], wy1, __hmul2(a[j], wy0));
}

// Sample one output pixel (both batches) for kernel tap k -> 4+4 half2
__device__ __forceinline__ void sample_pix(int k, int4 si, uint4 hw, int w, int h,
                                           __half2* o0, __half2* o1) {
    if (k == 4) {
        // center tap: exact identity sample
        int i = h * WW + w;
        uint4 P = g_h[i];
        uint4 Q = g_h[HW + i];
        const __half2* p = reinterpret_cast<const __half2*>(&P);
        const __half2* q = reinterpret_cast<const __half2*>(&Q);
#pragma unroll
        for (int j = 0; j < 4; j++) { o0[j] = p[j]; o1[j] = q[j]; }
    } else {
        int ix0 = (w + si.x) & (WW - 1);
        bool axis = ((k == 1) || (k == 7)) && si.w;
        if (axis) {
            blend2h(g_h[si.y + ix0], g_h[si.z + ix0], u2h2(hw.x), u2h2(hw.z), o0);
            blend2h(g_h[HW + si.y + ix0], g_h[HW + si.z + ix0], u2h2(hw.x), u2h2(hw.z), o1);
        } else {
            int ix1 = (ix0 + 1) & (WW - 1);
            blend4h(g_h[si.y + ix0], g_h[si.y + ix1],
                    g_h[si.z + ix0], g_h[si.z + ix1],
                    u2h2(hw.x), u2h2(hw.y), u2h2(hw.z), u2h2(hw.w), o0);
            blend4h(g_h[HW + si.y + ix0], g_h[HW + si.y + ix1],
                    g_h[HW + si.z + ix0], g_h[HW + si.z + ix1],
                    u2h2(hw.x), u2h2(hw.y), u2h2(hw.z), u2h2(hw.w), o1);
        }
    }
}

__global__ __launch_bounds__(256, 3) void sconv_kernel(const float* __restrict__ wgt,
                                                       const float* __restrict__ bias,
                                                       float* __restrict__ out) {
    constexpr float PI_F = 3.14159265358979323846f;
    __shared__ __align__(16) float ws[KK * CC * OC];  // [k][c][o]
    __shared__ __align__(16) int4  s_i[16][KK];       // {mxi, y0*W, y1*W, axis}
    __shared__ __align__(16) uint4 s_hw[16][KK];      // half2 weights {w00,w01,w10,w11}
    __shared__ float sb[OC];

    int lane = threadIdx.x;
    int ty = threadIdx.y;
    int tid = ty * 32 + lane;

    for (int i = tid; i < KK * CC * OC; i += 256) {
        int k = i >> 6;
        int c = (i >> 3) & 7;
        int o = i & 7;
        ws[i] = wgt[(o * CC + c) * KK + k];
    }
    if (tid < OC) sb[tid] = bias[tid];

    // Per-(h,k) warp-uniform geometry for 16 rows of this block.
    if (tid < 16 * KK) {
        int tr = tid / KK;
        int k = tid - tr * KK;
        int h = blockIdx.y * 16 + tr;
        const float scale = PI_F / (float)HH;
        const float gx_scale = (float)WW / (2.0f * PI_F);
        const float gy_scale = (float)HH / PI_F;
        float po = PI_F * ((float)(2 * h + 1) * (0.5f / HH));
        float sp, cp;
        sincosf(po, &sp, &cp);
        float dx = (float)(k % KX - 1) * scale;
        float dy = (float)(k / KX - 1) * scale;
        float alpha = fmaf(cp, dy, sp);
        float gamma = fmaf(-sp, dy, cp);
        float r = sqrtf(fmaf(alpha, alpha, dx * dx));
        float pol = fast_atan2f(r, gamma);
        float phi = fast_atan2f(dx, alpha);
        float gy = pol * gy_scale - 0.5f;
        int iy0 = __float2int_rd(gy);
        float fy = gy - (float)iy0;
        int iy1 = min(iy0 + 1, HH - 1);
        iy0 = max(iy0, 0);
        float phi_px = phi * gx_scale;
        int mxi = __float2int_rd(phi_px);
        float fx = phi_px - (float)mxi;
        int axis = (phi_px == 0.0f) ? 1 : 0;
        float wx0 = 1.0f - fx, fy0 = 1.0f - fy;
        __half2 h00 = __float2half2_rn(wx0 * fy0);
        __half2 h01 = __float2half2_rn(fx * fy0);
        __half2 h10 = __float2half2_rn(wx0 * fy);
        __half2 h11 = __float2half2_rn(fx * fy);
        s_i[tr][k] = make_int4(mxi, iy0 * WW, iy1 * WW, axis);
        uint4 hw;
        hw.x = *reinterpret_cast<unsigned*>(&h00);
        hw.y = *reinterpret_cast<unsigned*>(&h01);
        hw.z = *reinterpret_cast<unsigned*>(&h10);
        hw.w = *reinterpret_cast<unsigned*>(&h11);
        s_hw[tr][k] = hw;
    }
    __syncthreads();

    int w = blockIdx.x * 32 + lane;
    int hA = blockIdx.y * 16 + ty;
    int hB = hA + 8;

    // Accumulators: 4 o-pairs per (pixel, batch), bias folded in.
    unsigned long long aA0[4], aA1[4], aB0[4], aB1[4];
    const unsigned long long* sbp = reinterpret_cast<const unsigned long long*>(sb);
#pragma unroll
    for (int j = 0; j < 4; j++) {
        unsigned long long b = sbp[j];
        aA0[j] = b; aA1[j] = b; aB0[j] = b; aB1[j] = b;
    }

    const ulonglong2* wsp = reinterpret_cast<const ulonglong2*>(ws);

#pragma unroll
    for (int k = 0; k < KK; k++) {
        __half2 hA0[4], hA1[4], hB0[4], hB1[4];
        sample_pix(k, s_i[ty][k], s_hw[ty][k], w, hA, hA0, hA1);
        sample_pix(k, s_i[ty + 8][k], s_hw[ty + 8][k], w, hB, hB0, hB1);

        const ulonglong2* wk = wsp + k * 16;
#pragma unroll
        for (int j = 0; j < 4; j++) {
            float2 fA0 = __half22float2(hA0[j]);
            float2 fA1 = __half22float2(hA1[j]);
            float2 fB0 = __half22float2(hB0[j]);
            float2 fB1 = __half22float2(hB1[j]);
#pragma unroll
            for (int t = 0; t < 2; t++) {
                int c = 2 * j + t;
                ulonglong2 wa = wk[c * 2 + 0]; // (o0,o1),(o2,o3)
                ulonglong2 wb = wk[c * 2 + 1]; // (o4,o5),(o6,o7)
                float vA0 = t ? fA0.y : fA0.x;
                float vA1 = t ? fA1.y : fA1.x;
                float vB0 = t ? fB0.y : fB0.x;
                float vB1 = t ? fB1.y : fB1.x;
                unsigned long long dA0 = dup_f32x2(vA0);
                unsigned long long dA1 = dup_f32x2(vA1);
                unsigned long long dB0 = dup_f32x2(vB0);
                unsigned long long dB1 = dup_f32x2(vB1);
                ffma2(aA0[0], dA0, wa.x); ffma2(aA0[1], dA0, wa.y);
                ffma2(aA0[2], dA0, wb.x); ffma2(aA0[3], dA0, wb.y);
                ffma2(aA1[0], dA1, wa.x); ffma2(aA1[1], dA1, wa.y);
                ffma2(aA1[2], dA1, wb.x); ffma2(aA1[3], dA1, wb.y);
                ffma2(aB0[0], dB0, wa.x); ffma2(aB0[1], dB0, wa.y);
                ffma2(aB0[2], dB0, wb.x); ffma2(aB0[3], dB0, wb.y);
                ffma2(aB1[0], dB1, wa.x); ffma2(aB1[1], dB1, wa.y);
                ffma2(aB1[2], dB1, wb.x); ffma2(aB1[3], dB1, wb.y);
            }
        }
    }

#pragma unroll
    for (int j = 0; j < 4; j++) {
        int o = 2 * j;
        float l, hi;
        asm("mov.b64 {%0, %1}, %2;" : "=f"(l), "=f"(hi) : "l"(aA0[j]));
        out[(size_t)((0 * OC + o) * HH + hA) * WW + w]     = l;
        out[(size_t)((0 * OC + o + 1) * HH + hA) * WW + w] = hi;
        asm("mov.b64 {%0, %1}, %2;" : "=f"(l), "=f"(hi) : "l"(aA1[j]));
        out[(size_t)((1 * OC + o) * HH + hA) * WW + w]     = l;
        out[(size_t)((1 * OC + o + 1) * HH + hA) * WW + w] = hi;
        asm("mov.b64 {%0, %1}, %2;" : "=f"(l), "=f"(hi) : "l"(aB0[j]));
        out[(size_t)((0 * OC + o) * HH + hB) * WW + w]     = l;
        out[(size_t)((0 * OC + o + 1) * HH + hB) * WW + w] = hi;
        asm("mov.b64 {%0, %1}, %2;" : "=f"(l), "=f"(hi) : "l"(aB1[j]));
        out[(size_t)((1 * OC + o) * HH + hB) * WW + w]     = l;
        out[(size_t)((1 * OC + o + 1) * HH + hB) * WW + w] = hi;
    }
}

extern "C" void kernel_launch(void* const* d_in, const int* in_sizes, int n_in,
                              void* d_out, int out_size) {
    const float* x = (const float*)d_in[0];
    const float* wgt = (const float*)d_in[1];
    const float* bias = (const float*)d_in[2];
    float* out = (float*)d_out;

    int npix = BB * HW;
    transpose_h<<<(npix + 255) / 256, 256>>>(x);

    dim3 block(32, 8);
    dim3 grid(WW / 32, HH / 16);
    sconv_kernel<<<grid, block>>>(wgt, bias, out);
}

// round 11
// speedup vs baseline: 1.1927x; 1.1927x over previous
#include <cuda_runtime.h>
#include <cuda_fp16.h>

#define BB 2
#define CC 8
#define HH 512
#define WW 1024
#define OC 8
#define KY 3
#define KX 3
#define KK (KY*KX)
#define HW (HH*WW)

// fp16 transposed input: [b][pix] -> 8 channels packed in 16 bytes.
__device__ __align__(16) uint4 g_h[(size_t)BB * HW];
// staging for weight relayout [k][c][o]
__device__ __align__(16) float g_wstage[KK * CC * OC];

__constant__ __align__(16) float c_ws[KK * CC * OC]; // [k][c][o]
__constant__ __align__(16) float c_sb[OC];

__global__ __launch_bounds__(256) void transpose_h(const float* __restrict__ x) {
    int idx = blockIdx.x * 256 + threadIdx.x;
    if (idx >= BB * HW) return;
    int b = idx >> 19;
    int hw = idx & (HW - 1);
    const float* xp = x + (size_t)b * CC * HW + hw;
    __half2 p0 = __floats2half2_rn(xp[0 * HW], xp[1 * HW]);
    __half2 p1 = __floats2half2_rn(xp[2 * HW], xp[3 * HW]);
    __half2 p2 = __floats2half2_rn(xp[4 * HW], xp[5 * HW]);
    __half2 p3 = __floats2half2_rn(xp[6 * HW], xp[7 * HW]);
    uint4 q;
    q.x = *reinterpret_cast<unsigned*>(&p0);
    q.y = *reinterpret_cast<unsigned*>(&p1);
    q.z = *reinterpret_cast<unsigned*>(&p2);
    q.w = *reinterpret_cast<unsigned*>(&p3);
    g_h[idx] = q;
}

__global__ void repack_w(const float* __restrict__ wgt) {
    int i = threadIdx.x; // 0..575
    if (i >= KK * CC * OC) return;
    int k = i >> 6;
    int c = (i >> 3) & 7;
    int o = i & 7;
    g_wstage[i] = wgt[(o * CC + c) * KK + k];
}

// atan2 with single fast division + Cephes poly. ~1e-7 rad error.
// Returns exactly +/-0 when y == 0 and x > 0 (relied on for the fx==0 path).
__device__ __forceinline__ float fast_atan2f(float y, float x) {
    float ay = fabsf(y), ax = fabsf(x);
    float n = fminf(ay, ax), d = fmaxf(ay, ax);
    bool big = n > 0.4142135624f * d;
    float num = big ? (n - d) : n;
    float den = big ? (n + d) : d;
    float t = __fdividef(num, den);
    float z = t * t;
    float p = fmaf(fmaf(fmaf(8.05374449538e-2f, z, -1.38776856032e-1f), z,
                        1.99777106478e-1f), z, -3.33329491539e-1f);
    float r = fmaf(p * z, t, t);
    if (big) r += 0.78539816339744831f;
    if (ay > ax) r = 1.57079632679489662f - r;
    if (x < 0.0f) r = 3.14159265358979323f - r;
    return copysignf(r, y);
}

__device__ __forceinline__ unsigned long long dup_f32x2(float f) {
    unsigned long long r;
    asm("mov.b64 %0, {%1, %1};" : "=l"(r) : "f"(f));
    return r;
}

__device__ __forceinline__ void ffma2(unsigned long long& acc,
                                      unsigned long long a, unsigned long long b) {
    asm("fma.rn.f32x2 %0, %1, %2, %0;" : "+l"(acc) : "l"(a), "l"(b));
}

__device__ __forceinline__ __half2 u2h2(unsigned u) { return *reinterpret_cast<__half2*>(&u); }

// 4-tap bilinear over 8 fp16 channels -> 8 fp32
__device__ __forceinline__ void bilin4(uint4 A, uint4 B, uint4 C, uint4 D,
                                       __half2 w00, __half2 w01, __half2 w10, __half2 w11,
                                       float* v) {
    const __half2* a = reinterpret_cast<const __half2*>(&A);
    const __half2* b = reinterpret_cast<const __half2*>(&B);
    const __half2* c = reinterpret_cast<const __half2*>(&C);
    const __half2* d = reinterpret_cast<const __half2*>(&D);
#pragma unroll
    for (int j = 0; j < 4; j++) {
        __half2 t = __hmul2(a[j], w00);
        t = __hfma2(b[j], w01, t);
        t = __hfma2(c[j], w10, t);
        t = __hfma2(d[j], w11, t);
        float2 f = __half22float2(t);
        v[2 * j]     = f.x;
        v[2 * j + 1] = f.y;
    }
}

// 2-tap (y only): fx == 0 exact path
__device__ __forceinline__ void bilin2(uint4 A, uint4 B,
                                       __half2 wy0, __half2 wy1, float* v) {
    const __half2* a = reinterpret_cast<const __half2*>(&A);
    const __half2* b = reinterpret_cast<const __half2*>(&B);
#pragma unroll
    for (int j = 0; j < 4; j++) {
        __half2 t = __hfma2(b[j], wy1, __hmul2(a[j], wy0));
        float2 f = __half22float2(t);
        v[2 * j]     = f.x;
        v[2 * j + 1] = f.y;
    }
}

// direct convert of one pixel (exact center tap)
__device__ __forceinline__ void cvt8(uint4 A, float* v) {
    const __half2* a = reinterpret_cast<const __half2*>(&A);
#pragma unroll
    for (int j = 0; j < 4; j++) {
        float2 f = __half22float2(a[j]);
        v[2 * j]     = f.x;
        v[2 * j + 1] = f.y;
    }
}

__global__ __launch_bounds__(256, 4) void sconv_kernel(float* __restrict__ out) {
    constexpr float PI_F = 3.14159265358979323846f;
    __shared__ __align__(16) int4  s_i[8][KK];   // {mxi, y0*W, y1*W, axis_flag}
    __shared__ __align__(16) uint4 s_hw[8][KK];  // half2 weights {w00,w01,w10,w11}

    int lane = threadIdx.x;
    int ty = threadIdx.y;
    int tid = ty * 32 + lane;

    // Per-(h,k) warp-uniform geometry + packed bilinear weights.
    if (tid < 8 * KK) {
        int tr = tid / KK;
        int k = tid - tr * KK;
        int h = blockIdx.y * 8 + tr;
        const float scale = PI_F / (float)HH;
        const float gx_scale = (float)WW / (2.0f * PI_F);
        const float gy_scale = (float)HH / PI_F;
        float po = PI_F * ((float)(2 * h + 1) * (0.5f / HH));
        float sp, cp;
        sincosf(po, &sp, &cp);
        float dx = (float)(k % KX - 1) * scale;
        float dy = (float)(k / KX - 1) * scale;
        float alpha = fmaf(cp, dy, sp);
        float gamma = fmaf(-sp, dy, cp);
        float r = sqrtf(fmaf(alpha, alpha, dx * dx));
        float pol = fast_atan2f(r, gamma);
        float phi = fast_atan2f(dx, alpha);
        float gy = pol * gy_scale - 0.5f;
        int iy0 = __float2int_rd(gy);
        float fy = gy - (float)iy0;
        int iy1 = min(iy0 + 1, HH - 1);
        iy0 = max(iy0, 0);
        float phi_px = phi * gx_scale;
        int mxi = __float2int_rd(phi_px);
        float fx = phi_px - (float)mxi;
        int axis = (phi_px == 0.0f) ? 1 : 0;
        float wx0 = 1.0f - fx, fy0 = 1.0f - fy;
        __half2 h00 = __float2half2_rn(wx0 * fy0);
        __half2 h01 = __float2half2_rn(fx * fy0);
        __half2 h10 = __float2half2_rn(wx0 * fy);
        __half2 h11 = __float2half2_rn(fx * fy);
        s_i[tr][k] = make_int4(mxi, iy0 * WW, iy1 * WW, axis);
        uint4 hw;
        hw.x = *reinterpret_cast<unsigned*>(&h00);
        hw.y = *reinterpret_cast<unsigned*>(&h01);
        hw.z = *reinterpret_cast<unsigned*>(&h10);
        hw.w = *reinterpret_cast<unsigned*>(&h11);
        s_hw[tr][k] = hw;
    }
    __syncthreads();

    int w = blockIdx.x * 32 + lane;
    int h = blockIdx.y * 8 + ty;

    unsigned long long a0[4], a1[4];
    const unsigned long long* sbp = reinterpret_cast<const unsigned long long*>(c_sb);
#pragma unroll
    for (int j = 0; j < 4; j++) { a0[j] = sbp[j]; a1[j] = sbp[j]; }

    const ulonglong2* wsp = reinterpret_cast<const ulonglong2*>(c_ws);

#pragma unroll
    for (int k = 0; k < KK; k++) {
        float v0[8], v1[8];

        if (k == 4) {
            // center tap: exact identity sample
            int i = h * WW + w;
            cvt8(g_h[i], v0);
            cvt8(g_h[HW + i], v1);
        } else {
            int4 si = s_i[ty][k];
            uint4 hw = s_hw[ty][k];
            int ix0 = (w + si.x) & (WW - 1);
            bool axis = ((k == 1) || (k == 7)) && si.w;
            if (axis) {
                bilin2(g_h[si.y + ix0], g_h[si.z + ix0], u2h2(hw.x), u2h2(hw.z), v0);
                bilin2(g_h[HW + si.y + ix0], g_h[HW + si.z + ix0], u2h2(hw.x), u2h2(hw.z), v1);
            } else {
                int ix1 = (ix0 + 1) & (WW - 1);
                bilin4(g_h[si.y + ix0], g_h[si.y + ix1],
                       g_h[si.z + ix0], g_h[si.z + ix1],
                       u2h2(hw.x), u2h2(hw.y), u2h2(hw.z), u2h2(hw.w), v0);
                bilin4(g_h[HW + si.y + ix0], g_h[HW + si.y + ix1],
                       g_h[HW + si.z + ix0], g_h[HW + si.z + ix1],
                       u2h2(hw.x), u2h2(hw.y), u2h2(hw.z), u2h2(hw.w), v1);
            }
        }

        const ulonglong2* wk = wsp + k * 16;
#pragma unroll
        for (int c = 0; c < CC; c++) {
            ulonglong2 wa = wk[c * 2 + 0]; // (o0,o1),(o2,o3)
            ulonglong2 wb = wk[c * 2 + 1]; // (o4,o5),(o6,o7)
            unsigned long long vd0 = dup_f32x2(v0[c]);
            unsigned long long vd1 = dup_f32x2(v1[c]);
            ffma2(a0[0], vd0, wa.x);
            ffma2(a0[1], vd0, wa.y);
            ffma2(a0[2], vd0, wb.x);
            ffma2(a0[3], vd0, wb.y);
            ffma2(a1[0], vd1, wa.x);
            ffma2(a1[1], vd1, wa.y);
            ffma2(a1[2], vd1, wb.x);
            ffma2(a1[3], vd1, wb.y);
        }
    }

#pragma unroll
    for (int j = 0; j < 4; j++) {
        float l0, h0, l1, h1;
        asm("mov.b64 {%0, %1}, %2;" : "=f"(l0), "=f"(h0) : "l"(a0[j]));
        asm("mov.b64 {%0, %1}, %2;" : "=f"(l1), "=f"(h1) : "l"(a1[j]));
        int o = 2 * j;
        out[(size_t)((0 * OC + o) * HH + h) * WW + w]     = l0;
        out[(size_t)((0 * OC + o + 1) * HH + h) * WW + w] = h0;
        out[(size_t)((1 * OC + o) * HH + h) * WW + w]     = l1;
        out[(size_t)((1 * OC + o + 1) * HH + h) * WW + w] = h1;
    }
}

extern "C" void kernel_launch(void* const* d_in, const int* in_sizes, int n_in,
                              void* d_out, int out_size) {
    const float* x = (const float*)d_in[0];
    const float* wgt = (const float*)d_in[1];
    const float* bias = (const float*)d_in[2];
    float* out = (float*)d_out;

    int npix = BB * HW;
    transpose_h<<<(npix + 255) / 256, 256>>>(x);

    repack_w<<<1, KK * CC * OC>>>(wgt);

    // Resolve the staging buffer's real device address (query only — no alloc).
    void* wstage_dev = nullptr;
    cudaGetSymbolAddress(&wstage_dev, g_wstage);

    // D2D memcpy nodes (graph-capturable, allocation-free)
    cudaMemcpyToSymbolAsync(c_ws, wstage_dev, KK * CC * OC * sizeof(float), 0,
                            cudaMemcpyDeviceToDevice);
    cudaMemcpyToSymbolAsync(c_sb, bias, OC * sizeof(float), 0,
                            cudaMemcpyDeviceToDevice);

    dim3 block(32, 8);
    dim3 grid(WW / 32, HH / 8);
    sconv_kernel<<<grid, block>>>(out);
}